// round 15
// baseline (speedup 1.0000x reference)
#include <cuda_runtime.h>
#include <cuda_fp16.h>

#define BB 256
#define TT 512
#define FF 128
#define HH 512
#define G4 2048
#define NBLK 128
#define ASTR 132                   // floats/row; 132 % 32 == 4 -> scalar LDS conflict-free
#define ABUF (64 * ASTR)
#define ZSTRH 72                   // halves/row; banks 4*gid+tg distinct
#define SM_A 131072                // after 32768-float U region
#define SM_Z 198656                // after 2 x ABUF floats
#define SM_TOT 207872

__device__ float g_h[2][BB * HH];                   // h, natural layout
__device__ __half g_zx[(size_t)TT * BB * 64 * 32];  // [t][cbi][b][64], fp16
__device__ unsigned char g_mask[TT * BB];
__device__ unsigned g_cnt;
__device__ unsigned g_flag2[4][4][32];              // [rbi][chunk][pad 128B]

#define U32 __float_as_uint

static __device__ __forceinline__ unsigned f2tf(float f) {
    unsigned u; asm("cvt.rna.tf32.f32 %0, %1;" : "=r"(u) : "f"(f)); return u;
}
static __device__ __forceinline__ float sigf(float x) {
    float t; asm("tanh.approx.f32 %0, %1;" : "=f"(t) : "f"(x * 0.5f));
    return fmaf(t, 0.5f, 0.5f);
}
static __device__ __forceinline__ void cpa(unsigned d, const void* g) {
    asm volatile("cp.async.cg.shared.global [%0],[%1],16;" :: "r"(d), "l"(g) : "memory");
}
static __device__ __forceinline__ void cp_commit() { asm volatile("cp.async.commit_group;" ::: "memory"); }
template <int N> static __device__ __forceinline__ void cp_wait() {
    asm volatile("cp.async.wait_group %0;" :: "n"(N) : "memory");
}
static __device__ __forceinline__ void pollflag(const unsigned* p, unsigned tgt) {
    unsigned v;
    while (1) {
        asm volatile("ld.acquire.gpu.global.b32 %0, [%1];" : "=r"(v) : "l"(p) : "memory");
        if (v >= tgt) break;
        asm volatile("nanosleep.u32 32;");
    }
}
static __device__ __forceinline__ void relflag(unsigned* p) {
    asm volatile("red.release.gpu.global.add.u32 [%0], %1;" :: "l"(p), "r"(1u) : "memory");
}
static __device__ __forceinline__ void mma8(float* c, unsigned a0, unsigned a1, unsigned a2,
                                            unsigned a3, unsigned b0, unsigned b1) {
    asm volatile(
        "mma.sync.aligned.m16n8k8.row.col.f32.tf32.tf32.f32 "
        "{%0,%1,%2,%3},{%4,%5,%6,%7},{%8,%9},{%0,%1,%2,%3};"
        : "+f"(c[0]), "+f"(c[1]), "+f"(c[2]), "+f"(c[3])
        : "r"(a0), "r"(a1), "r"(a2), "r"(a3), "r"(b0), "r"(b1));
}

__global__ void zero_cnt() {
    if (threadIdx.x == 0) g_cnt = 0u;
    unsigned* f = &g_flag2[0][0][0];
    for (int i = threadIdx.x; i < 4 * 4 * 32; i += 32) f[i] = 0u;
}

__global__ void mask_kernel(const float* __restrict__ x) {
    int wid = (blockIdx.x * blockDim.x + threadIdx.x) >> 5;
    int lane = threadIdx.x & 31;
    int b = wid >> 9, t = wid & 511;
    float4 v = *(const float4*)(x + (size_t)wid * FF + lane * 4);
    bool any = (v.x != -1.f) | (v.y != -1.f) | (v.z != -1.f) | (v.w != -1.f);
    unsigned m = __ballot_sync(0xffffffffu, any);
    if (lane == 0) g_mask[t * BB + b] = (m != 0u);
}

// zx = x@W + b. Grid (32, 1024): cbi fastest so 32 cbi-blocks share one x tile in L2.
__global__ void __launch_bounds__(128) zx_gemm(const float* __restrict__ x,
                                               const float* __restrict__ W,
                                               const float* __restrict__ bias) {
    extern __shared__ float sm[];
    float* xs = sm;             // [128][132]
    float* ws = sm + 16896;     // [128][72]
    const int tid = threadIdx.x;
    const int cbi = blockIdx.x;
    const int b = blockIdx.y >> 2, tt = blockIdx.y & 3;
    const int hc0 = cbi * 16;
    const unsigned xsA = (unsigned)__cvta_generic_to_shared(xs);
    const unsigned wsA = (unsigned)__cvta_generic_to_shared(ws);

    #pragma unroll 4
    for (int q = 0; q < 32; ++q) {
        int fi = q * 128 + tid, r = fi >> 5, s = (fi & 31) * 4;
        cpa(xsA + (r * 132 + s) * 4, x + ((size_t)b * TT + tt * 128 + r) * FF + s);
    }
    #pragma unroll 4
    for (int q = 0; q < 16; ++q) {
        int fi = q * 128 + tid, k = fi >> 4, c = (fi & 15) * 4;
        cpa(wsA + (k * 72 + c) * 4, W + (size_t)k * G4 + (c >> 4) * HH + hc0 + (c & 15));
    }
    cp_commit(); cp_wait<0>(); __syncthreads();

    const int warp = tid >> 5, lane = tid & 31;
    const int gid = lane >> 2, tg = lane & 3;
    float acc[2][8][4];
    #pragma unroll
    for (int m = 0; m < 2; ++m)
        #pragma unroll
        for (int n = 0; n < 8; ++n)
            #pragma unroll
            for (int q = 0; q < 4; ++q) acc[m][n][q] = 0.f;

    #pragma unroll
    for (int k8 = 0; k8 < 16; ++k8) {
        float a[2][4];
        #pragma unroll
        for (int mt = 0; mt < 2; ++mt) {
            int base = (warp * 32 + mt * 16 + gid) * 132 + k8 * 8 + tg;
            a[mt][0] = xs[base];           a[mt][1] = xs[base + 8 * 132];
            a[mt][2] = xs[base + 4];       a[mt][3] = xs[base + 8 * 132 + 4];
        }
        #pragma unroll
        for (int nt = 0; nt < 8; ++nt) {
            float b0 = ws[(k8 * 8 + tg) * 72 + nt * 8 + gid];
            float b1 = ws[(k8 * 8 + tg + 4) * 72 + nt * 8 + gid];
            #pragma unroll
            for (int mt = 0; mt < 2; ++mt)
                mma8(acc[mt][nt], U32(a[mt][0]), U32(a[mt][1]), U32(a[mt][2]),
                     U32(a[mt][3]), U32(b0), U32(b1));
        }
    }
    #pragma unroll
    for (int mt = 0; mt < 2; ++mt)
        #pragma unroll
        for (int hi = 0; hi < 2; ++hi) {
            int r = warp * 32 + mt * 16 + gid + hi * 8;
            int t = tt * 128 + r;
            #pragma unroll
            for (int nt = 0; nt < 8; ++nt) {
                int c = nt * 8 + 2 * tg;
                int gc = (c >> 4) * HH + hc0 + (c & 15);
                float v0 = acc[mt][nt][hi * 2 + 0] + __ldg(bias + gc);
                float v1 = acc[mt][nt][hi * 2 + 1] + __ldg(bias + gc + 1);
                *(__half2*)&g_zx[(((size_t)t * 32 + cbi) * BB + b) * 64 + c] =
                    __floats2half2_rn(v0, v1);
            }
        }
}

// Persistent recurrent kernel: 128 blocks x 128 threads (4 warps 2M x 2N).
// Per-chunk producer flags: chunk ch (128 h-cols) produced by cbi in [8ch, 8ch+8).
__global__ void __launch_bounds__(128, 1) lstm_persist(const float* __restrict__ U) {
    extern __shared__ char smc[];
    const unsigned sb = (unsigned)__cvta_generic_to_shared(smc);
    float4* Us4 = (float4*)smc;                     // 32768 floats: packed B-frags
    float* As = (float*)(smc + SM_A);               // 2 x ABUF (128-col chunks)
    __half* Zsh = (__half*)(smc + SM_Z);            // 64 x ZSTRH halves

    const int tid = threadIdx.x;
    const int rbi = blockIdx.x & 3, rb = rbi * 64;
    const int cbi = blockIdx.x >> 2, hc0 = cbi * 16;
    const int warp = tid >> 5, lane = tid & 31;
    const int wm = warp >> 1, wn = warp & 1;
    const int gid = lane >> 2, tg = lane & 3;
    unsigned* myflag = &g_flag2[rbi][cbi >> 3][0];

    // --- pack U slice into tf32 B-fragment order (proven) ---
    for (int idx = tid; idx < 64 * HH; idx += 128) {
        int k = idx >> 6, c = idx & 63;
        int gcol = (c >> 4) * HH + hc0 + (c & 15);
        unsigned v = f2tf(__ldg(&U[(size_t)k * G4 + gcol]));
        int n8 = c >> 3, g = c & 7, k8 = k >> 3, kk = k & 7;
        int f = k8 >> 1, slot = (k8 & 1) * 2 + (kk >> 2), ln = g * 4 + (kk & 3);
        ((float*)smc)[(((n8 * 32 + f) * 32 + ln) << 2) + slot] = __uint_as_float(v);
    }
    // --- zero phase-0 h ---
    for (int i = tid; i < 1024; i += 128) g_h[0][blockIdx.x * 1024 + i] = 0.f;

    __syncthreads();
    if (tid == 0) {
        __threadfence();
        atomicAdd(&g_cnt, 1u);
        while (*(volatile unsigned*)&g_cnt < NBLK) { asm volatile("nanosleep.u32 64;"); }
        __threadfence();
    }
    __syncthreads();

    float cR[8], hR[8];
    #pragma unroll
    for (int i = 0; i < 8; ++i) { cR[i] = 0.f; hR[i] = 0.f; }

    for (int t = 0; t < TT; ++t) {
        const float* hin = g_h[t & 1];
        float* hout = g_h[(t + 1) & 1];
        const __half* zsrc = g_zx + (((size_t)t * 32 + cbi) * BB + rb) * 64;
        const unsigned ftgt = 8u * (unsigned)t;

        #pragma unroll
        for (int q = 0; q < 4; ++q) {   // stage zx tile (8KB fp16, no cross-block dep)
            int fi = q * 128 + tid, r = fi >> 3, s2 = (fi & 7) * 8;
            cpa(sb + SM_Z + r * (ZSTRH * 2) + s2 * 2, zsrc + r * 64 + s2);
        }

        if (t > 0 && tid == 0) pollflag(&g_flag2[rbi][0][0], ftgt);
        __syncthreads();

#define STAGE_A(ch)                                                             \
        do {                                                                    \
            unsigned dst = sb + SM_A + ((ch) & 1) * (ABUF * 4);                 \
            _Pragma("unroll")                                                   \
            for (int q = 0; q < 16; ++q) {                                      \
                int fi = q * 128 + tid, r = fi >> 5, s = (fi & 31) * 4;         \
                cpa(dst + (r * ASTR + s) * 4,                                   \
                    hin + (size_t)(rb + r) * HH + (ch) * 128 + s);              \
            }                                                                   \
            cp_commit();                                                        \
        } while (0)

        STAGE_A(0);   // commits Z too

        float acc[2][4][4];
        #pragma unroll
        for (int m = 0; m < 2; ++m)
            #pragma unroll
            for (int n = 0; n < 4; ++n)
                #pragma unroll
                for (int q = 0; q < 4; ++q) acc[m][n][q] = 0.f;

        for (int ch = 0; ch < 4; ++ch) {
            // poll next chunk's producers while this chunk's data arrives
            if (t > 0 && tid == 0 && ch + 1 < 4)
                pollflag(&g_flag2[rbi][ch + 1][0], ftgt);
            cp_wait<0>();
            __syncthreads();                 // A(ch) visible to all; buf (ch+1)&1 free
            if (ch + 1 < 4) STAGE_A(ch + 1); // race-free: everyone past mma(ch-1)
            const float* Ab = As + (ch & 1) * ABUF;
            #pragma unroll
            for (int fl = 0; fl < 8; ++fl) {
                float a[2][2][4];
                #pragma unroll
                for (int e = 0; e < 2; ++e) {
                    int kl = (fl * 2 + e) * 8;
                    #pragma unroll
                    for (int mt = 0; mt < 2; ++mt) {
                        int base = (wm * 32 + mt * 16 + gid) * ASTR + kl + tg;
                        a[e][mt][0] = Ab[base];      a[e][mt][1] = Ab[base + 8 * ASTR];
                        a[e][mt][2] = Ab[base + 4];  a[e][mt][3] = Ab[base + 8 * ASTR + 4];
                    }
                }
                #pragma unroll
                for (int nt = 0; nt < 4; ++nt) {    // nt = gate; colgroup = nt*2 + wn
                    float4 bq = Us4[((nt * 2 + wn) * 32 + ch * 8 + fl) * 32 + lane];
                    #pragma unroll
                    for (int mt = 0; mt < 2; ++mt) {
                        mma8(acc[mt][nt], U32(a[0][mt][0]), U32(a[0][mt][1]),
                             U32(a[0][mt][2]), U32(a[0][mt][3]), U32(bq.x), U32(bq.y));
                        mma8(acc[mt][nt], U32(a[1][mt][0]), U32(a[1][mt][1]),
                             U32(a[1][mt][2]), U32(a[1][mt][3]), U32(bq.z), U32(bq.w));
                    }
                }
            }
        }

        // --- warp-local epilogue ---
        #pragma unroll
        for (int mt = 0; mt < 2; ++mt)
            #pragma unroll
            for (int hi = 0; hi < 2; ++hi) {
                int row = wm * 32 + mt * 16 + gid + hi * 8;
                int grow = rb + row;
                bool m = g_mask[t * BB + grow] != 0;
                int jb = wn * 8 + 2 * tg;
                const __half2* Zr = (const __half2*)(Zsh + row * ZSTRH);
                float2 zi2 = __half22float2(Zr[(jb >> 1)]);
                float2 zf2 = __half22float2(Zr[(jb >> 1) + 8]);
                float2 zg2 = __half22float2(Zr[(jb >> 1) + 16]);
                float2 zo2 = __half22float2(Zr[(jb >> 1) + 24]);
                float2 hv2;
                #pragma unroll
                for (int jj = 0; jj < 2; ++jj) {
                    int cq = hi * 2 + jj;
                    float zi = acc[mt][0][cq] + (jj ? zi2.y : zi2.x);
                    float zf = acc[mt][1][cq] + (jj ? zf2.y : zf2.x);
                    float zg = acc[mt][2][cq] + (jj ? zg2.y : zg2.x);
                    float zo = acc[mt][3][cq] + (jj ? zo2.y : zo2.x);
                    float iv = sigf(zi), fv = sigf(zf);
                    float gv = fmaxf(zg, 0.f), ov = sigf(zo);
                    int s = mt * 4 + hi * 2 + jj;
                    float cn = fv * cR[s] + iv * gv;
                    float hn = ov * fmaxf(cn, 0.f);
                    cR[s] = m ? cn : cR[s];
                    float hv = m ? hn : hR[s];
                    hR[s] = hv;
                    if (jj) hv2.y = hv; else hv2.x = hv;
                }
                *(float2*)&hout[(size_t)grow * HH + hc0 + jb] = hv2;
            }

        // --- release: bar (cumulativity) + elected release-atomic ---
        __syncthreads();
        if (tid == 0) relflag(myflag);
#undef STAGE_A
    }
}

__global__ void head_kernel(const float* __restrict__ Wd, const float* __restrict__ bd,
                            float* __restrict__ out) {
    const float* h = g_h[0];   // final h in phase 0 (512 even steps)
    const int warp = threadIdx.x >> 5, lane = threadIdx.x & 31;
    const int row = blockIdx.x * 8 + warp;
    float s = 0.f;
    #pragma unroll
    for (int k = lane; k < HH; k += 32) s += h[row * HH + k] * Wd[k];
    #pragma unroll
    for (int o = 16; o; o >>= 1) s += __shfl_xor_sync(0xffffffffu, s, o);
    if (lane == 0) out[row] = sigf(s + bd[0]);
}

extern "C" void kernel_launch(void* const* d_in, const int* in_sizes, int n_in,
                              void* d_out, int out_size) {
    const float* x  = (const float*)d_in[0];
    const float* W  = (const float*)d_in[1];
    const float* U  = (const float*)d_in[2];
    const float* b  = (const float*)d_in[3];
    const float* Wd = (const float*)d_in[4];
    const float* bd = (const float*)d_in[5];

    cudaFuncSetAttribute(zx_gemm, cudaFuncAttributeMaxDynamicSharedMemorySize, 104448);
    cudaFuncSetAttribute(lstm_persist, cudaFuncAttributeMaxDynamicSharedMemorySize, SM_TOT);

    mask_kernel<<<BB * TT / 8, 256>>>(x);
    zx_gemm<<<dim3(32, BB * 4), 128, 104448>>>(x, W, b);
    zero_cnt<<<1, 32>>>();
    lstm_persist<<<NBLK, 128, SM_TOT>>>(U);
    head_kernel<<<BB / 8, 256>>>(Wd, bd, (float*)d_out);
}

// round 16
// speedup vs baseline: 1.1717x; 1.1717x over previous
#include <cuda_runtime.h>
#include <cuda_fp16.h>

#define BB 256
#define TT 512
#define FF 128
#define HH 512
#define G4 2048
#define NBLK 128
#define ASTR 132                   // floats/row; 132 % 32 == 4 -> scalar LDS conflict-free
#define ABUF (64 * ASTR)
#define ZSTRH 72                   // halves/row; banks 4*gid+tg distinct
#define SM_A 131072                // after 32768-float U region
#define SM_Z 198656                // after 2 x ABUF floats
#define SM_TOT 207872

__device__ float g_h[2][BB * HH];                   // h, natural layout
__device__ __half g_zx[(size_t)TT * BB * 64 * 32];  // [t][cbi][b][64], fp16
__device__ unsigned char g_mask[TT * BB];
__device__ unsigned g_cnt;
__device__ unsigned g_flag[4][32];                  // per row-group counter, 128B apart

#define U32 __float_as_uint

static __device__ __forceinline__ unsigned f2tf(float f) {
    unsigned u; asm("cvt.rna.tf32.f32 %0, %1;" : "=r"(u) : "f"(f)); return u;
}
static __device__ __forceinline__ float sigf(float x) {
    float t; asm("tanh.approx.f32 %0, %1;" : "=f"(t) : "f"(x * 0.5f));
    return fmaf(t, 0.5f, 0.5f);
}
static __device__ __forceinline__ void cpa(unsigned d, const void* g) {
    asm volatile("cp.async.cg.shared.global [%0],[%1],16;" :: "r"(d), "l"(g) : "memory");
}
static __device__ __forceinline__ void cp_commit() { asm volatile("cp.async.commit_group;" ::: "memory"); }
template <int N> static __device__ __forceinline__ void cp_wait() {
    asm volatile("cp.async.wait_group %0;" :: "n"(N) : "memory");
}
static __device__ __forceinline__ void pollflag(const unsigned* p, unsigned tgt) {
    unsigned v;
    while (1) {
        asm volatile("ld.acquire.gpu.global.b32 %0, [%1];" : "=r"(v) : "l"(p) : "memory");
        if (v >= tgt) break;
        asm volatile("nanosleep.u32 32;");
    }
}
static __device__ __forceinline__ void relflag(unsigned* p) {
    asm volatile("red.release.gpu.global.add.u32 [%0], %1;" :: "l"(p), "r"(1u) : "memory");
}
static __device__ __forceinline__ void mma8(float* c, unsigned a0, unsigned a1, unsigned a2,
                                            unsigned a3, unsigned b0, unsigned b1) {
    asm volatile(
        "mma.sync.aligned.m16n8k8.row.col.f32.tf32.tf32.f32 "
        "{%0,%1,%2,%3},{%4,%5,%6,%7},{%8,%9},{%0,%1,%2,%3};"
        : "+f"(c[0]), "+f"(c[1]), "+f"(c[2]), "+f"(c[3])
        : "r"(a0), "r"(a1), "r"(a2), "r"(a3), "r"(b0), "r"(b1));
}

__global__ void zero_cnt() {
    if (threadIdx.x == 0) g_cnt = 0u;
    unsigned* f = &g_flag[0][0];
    for (int i = threadIdx.x; i < 4 * 32; i += 32) f[i] = 0u;
}

__global__ void mask_kernel(const float* __restrict__ x) {
    int wid = (blockIdx.x * blockDim.x + threadIdx.x) >> 5;
    int lane = threadIdx.x & 31;
    int b = wid >> 9, t = wid & 511;
    float4 v = *(const float4*)(x + (size_t)wid * FF + lane * 4);
    bool any = (v.x != -1.f) | (v.y != -1.f) | (v.z != -1.f) | (v.w != -1.f);
    unsigned m = __ballot_sync(0xffffffffu, any);
    if (lane == 0) g_mask[t * BB + b] = (m != 0u);
}

// zx = x@W + b. Grid (32, 1024): cbi fastest so 32 cbi-blocks share one x tile in L2.
__global__ void __launch_bounds__(128) zx_gemm(const float* __restrict__ x,
                                               const float* __restrict__ W,
                                               const float* __restrict__ bias) {
    extern __shared__ float sm[];
    float* xs = sm;             // [128][132]
    float* ws = sm + 16896;     // [128][72]
    const int tid = threadIdx.x;
    const int cbi = blockIdx.x;
    const int b = blockIdx.y >> 2, tt = blockIdx.y & 3;
    const int hc0 = cbi * 16;
    const unsigned xsA = (unsigned)__cvta_generic_to_shared(xs);
    const unsigned wsA = (unsigned)__cvta_generic_to_shared(ws);

    #pragma unroll 4
    for (int q = 0; q < 32; ++q) {
        int fi = q * 128 + tid, r = fi >> 5, s = (fi & 31) * 4;
        cpa(xsA + (r * 132 + s) * 4, x + ((size_t)b * TT + tt * 128 + r) * FF + s);
    }
    #pragma unroll 4
    for (int q = 0; q < 16; ++q) {
        int fi = q * 128 + tid, k = fi >> 4, c = (fi & 15) * 4;
        cpa(wsA + (k * 72 + c) * 4, W + (size_t)k * G4 + (c >> 4) * HH + hc0 + (c & 15));
    }
    cp_commit(); cp_wait<0>(); __syncthreads();

    const int warp = tid >> 5, lane = tid & 31;
    const int gid = lane >> 2, tg = lane & 3;
    float acc[2][8][4];
    #pragma unroll
    for (int m = 0; m < 2; ++m)
        #pragma unroll
        for (int n = 0; n < 8; ++n)
            #pragma unroll
            for (int q = 0; q < 4; ++q) acc[m][n][q] = 0.f;

    #pragma unroll
    for (int k8 = 0; k8 < 16; ++k8) {
        float a[2][4];
        #pragma unroll
        for (int mt = 0; mt < 2; ++mt) {
            int base = (warp * 32 + mt * 16 + gid) * 132 + k8 * 8 + tg;
            a[mt][0] = xs[base];           a[mt][1] = xs[base + 8 * 132];
            a[mt][2] = xs[base + 4];       a[mt][3] = xs[base + 8 * 132 + 4];
        }
        #pragma unroll
        for (int nt = 0; nt < 8; ++nt) {
            float b0 = ws[(k8 * 8 + tg) * 72 + nt * 8 + gid];
            float b1 = ws[(k8 * 8 + tg + 4) * 72 + nt * 8 + gid];
            #pragma unroll
            for (int mt = 0; mt < 2; ++mt)
                mma8(acc[mt][nt], U32(a[mt][0]), U32(a[mt][1]), U32(a[mt][2]),
                     U32(a[mt][3]), U32(b0), U32(b1));
        }
    }
    #pragma unroll
    for (int mt = 0; mt < 2; ++mt)
        #pragma unroll
        for (int hi = 0; hi < 2; ++hi) {
            int r = warp * 32 + mt * 16 + gid + hi * 8;
            int t = tt * 128 + r;
            #pragma unroll
            for (int nt = 0; nt < 8; ++nt) {
                int c = nt * 8 + 2 * tg;
                int gc = (c >> 4) * HH + hc0 + (c & 15);
                float v0 = acc[mt][nt][hi * 2 + 0] + __ldg(bias + gc);
                float v1 = acc[mt][nt][hi * 2 + 1] + __ldg(bias + gc + 1);
                *(__half2*)&g_zx[(((size_t)t * 32 + cbi) * BB + b) * 64 + c] =
                    __floats2half2_rn(v0, v1);
            }
        }
}

// Persistent recurrent kernel: 128 blocks x 128 threads (4 warps 2M x 2N).
// Mainloop math identical to the 4106us best; cheaper release + mask prefetch.
__global__ void __launch_bounds__(128, 1) lstm_persist(const float* __restrict__ U) {
    extern __shared__ char smc[];
    const unsigned sb = (unsigned)__cvta_generic_to_shared(smc);
    float4* Us4 = (float4*)smc;                     // 32768 floats: packed B-frags
    float* As = (float*)(smc + SM_A);               // 2 x ABUF (128-col chunks)
    __half* Zsh = (__half*)(smc + SM_Z);            // 64 x ZSTRH halves

    const int tid = threadIdx.x;
    const int rbi = blockIdx.x & 3, rb = rbi * 64;
    const int cbi = blockIdx.x >> 2, hc0 = cbi * 16;
    const int warp = tid >> 5, lane = tid & 31;
    const int wm = warp >> 1, wn = warp & 1;
    const int gid = lane >> 2, tg = lane & 3;

    // --- pack U slice into tf32 B-fragment order (proven) ---
    for (int idx = tid; idx < 64 * HH; idx += 128) {
        int k = idx >> 6, c = idx & 63;
        int gcol = (c >> 4) * HH + hc0 + (c & 15);
        unsigned v = f2tf(__ldg(&U[(size_t)k * G4 + gcol]));
        int n8 = c >> 3, g = c & 7, k8 = k >> 3, kk = k & 7;
        int f = k8 >> 1, slot = (k8 & 1) * 2 + (kk >> 2), ln = g * 4 + (kk & 3);
        ((float*)smc)[(((n8 * 32 + f) * 32 + ln) << 2) + slot] = __uint_as_float(v);
    }
    // --- zero phase-0 h ---
    for (int i = tid; i < 1024; i += 128) g_h[0][blockIdx.x * 1024 + i] = 0.f;

    __syncthreads();
    if (tid == 0) {
        __threadfence();
        atomicAdd(&g_cnt, 1u);
        while (*(volatile unsigned*)&g_cnt < NBLK) { asm volatile("nanosleep.u32 64;"); }
        __threadfence();
    }
    __syncthreads();

    float cR[8], hR[8];
    #pragma unroll
    for (int i = 0; i < 8; ++i) { cR[i] = 0.f; hR[i] = 0.f; }

    for (int t = 0; t < TT; ++t) {
        const float* hin = g_h[t & 1];
        float* hout = g_h[(t + 1) & 1];
        const __half* zsrc = g_zx + (((size_t)t * 32 + cbi) * BB + rb) * 64;

        #pragma unroll
        for (int q = 0; q < 4; ++q) {   // stage zx tile (8KB fp16, no cross-block dep)
            int fi = q * 128 + tid, r = fi >> 3, s2 = (fi & 7) * 8;
            cpa(sb + SM_Z + r * (ZSTRH * 2) + s2 * 2, zsrc + r * 64 + s2);
        }

        // --- mask prefetch: t-dependent only; overlaps staging + mma ---
        bool mk[4];
        #pragma unroll
        for (int mt = 0; mt < 2; ++mt)
            #pragma unroll
            for (int hi = 0; hi < 2; ++hi)
                mk[mt * 2 + hi] =
                    __ldg(&g_mask[t * BB + rb + wm * 32 + mt * 16 + gid + hi * 8]) != 0;

        // --- row-group sync: single acquire-poller, then block broadcast ---
        if (t > 0) {
            if (tid == 0) pollflag(&g_flag[rbi][0], 32u * (unsigned)t);
            __syncthreads();
        }

#define STAGE_A(ch)                                                             \
        do {                                                                    \
            unsigned dst = sb + SM_A + ((ch) & 1) * (ABUF * 4);                 \
            _Pragma("unroll")                                                   \
            for (int q = 0; q < 16; ++q) {                                      \
                int fi = q * 128 + tid, r = fi >> 5, s = (fi & 31) * 4;         \
                cpa(dst + (r * ASTR + s) * 4,                                   \
                    hin + (size_t)(rb + r) * HH + (ch) * 128 + s);              \
            }                                                                   \
        } while (0)

        STAGE_A(0); cp_commit();   // commits Z too

        float acc[2][4][4];
        #pragma unroll
        for (int m = 0; m < 2; ++m)
            #pragma unroll
            for (int n = 0; n < 4; ++n)
                #pragma unroll
                for (int q = 0; q < 4; ++q) acc[m][n][q] = 0.f;

        for (int ch = 0; ch < 4; ++ch) {
            if (ch + 1 < 4) { STAGE_A(ch + 1); cp_commit(); cp_wait<1>(); }
            else            { cp_wait<0>(); }
            __syncthreads();
            const float* Ab = As + (ch & 1) * ABUF;
            #pragma unroll
            for (int fl = 0; fl < 8; ++fl) {
                float a[2][2][4];
                #pragma unroll
                for (int e = 0; e < 2; ++e) {
                    int kl = (fl * 2 + e) * 8;
                    #pragma unroll
                    for (int mt = 0; mt < 2; ++mt) {
                        int base = (wm * 32 + mt * 16 + gid) * ASTR + kl + tg;
                        a[e][mt][0] = Ab[base];      a[e][mt][1] = Ab[base + 8 * ASTR];
                        a[e][mt][2] = Ab[base + 4];  a[e][mt][3] = Ab[base + 8 * ASTR + 4];
                    }
                }
                #pragma unroll
                for (int nt = 0; nt < 4; ++nt) {    // nt = gate; colgroup = nt*2 + wn
                    float4 bq = Us4[((nt * 2 + wn) * 32 + ch * 8 + fl) * 32 + lane];
                    #pragma unroll
                    for (int mt = 0; mt < 2; ++mt) {
                        mma8(acc[mt][nt], U32(a[0][mt][0]), U32(a[0][mt][1]),
                             U32(a[0][mt][2]), U32(a[0][mt][3]), U32(bq.x), U32(bq.y));
                        mma8(acc[mt][nt], U32(a[1][mt][0]), U32(a[1][mt][1]),
                             U32(a[1][mt][2]), U32(a[1][mt][3]), U32(bq.z), U32(bq.w));
                    }
                }
            }
        }

        // --- warp-local epilogue ---
        #pragma unroll
        for (int mt = 0; mt < 2; ++mt)
            #pragma unroll
            for (int hi = 0; hi < 2; ++hi) {
                int row = wm * 32 + mt * 16 + gid + hi * 8;
                int grow = rb + row;
                bool m = mk[mt * 2 + hi];
                int jb = wn * 8 + 2 * tg;
                const __half2* Zr = (const __half2*)(Zsh + row * ZSTRH);
                float2 zi2 = __half22float2(Zr[(jb >> 1)]);
                float2 zf2 = __half22float2(Zr[(jb >> 1) + 8]);
                float2 zg2 = __half22float2(Zr[(jb >> 1) + 16]);
                float2 zo2 = __half22float2(Zr[(jb >> 1) + 24]);
                float2 hv2;
                #pragma unroll
                for (int jj = 0; jj < 2; ++jj) {
                    int cq = hi * 2 + jj;
                    float zi = acc[mt][0][cq] + (jj ? zi2.y : zi2.x);
                    float zf = acc[mt][1][cq] + (jj ? zf2.y : zf2.x);
                    float zg = acc[mt][2][cq] + (jj ? zg2.y : zg2.x);
                    float zo = acc[mt][3][cq] + (jj ? zo2.y : zo2.x);
                    float iv = sigf(zi), fv = sigf(zf);
                    float gv = fmaxf(zg, 0.f), ov = sigf(zo);
                    int s = mt * 4 + hi * 2 + jj;
                    float cn = fv * cR[s] + iv * gv;
                    float hn = ov * fmaxf(cn, 0.f);
                    cR[s] = m ? cn : cR[s];
                    float hv = m ? hn : hR[s];
                    hR[s] = hv;
                    if (jj) hv2.y = hv; else hv2.x = hv;
                }
                *(float2*)&hout[(size_t)grow * HH + hc0 + jb] = hv2;
            }

        // --- release: bar (cumulativity) + elected release-atomic ---
        __syncthreads();
        if (tid == 0) relflag(&g_flag[rbi][0]);
#undef STAGE_A
    }
}

__global__ void head_kernel(const float* __restrict__ Wd, const float* __restrict__ bd,
                            float* __restrict__ out) {
    const float* h = g_h[0];   // final h in phase 0 (512 even steps)
    const int warp = threadIdx.x >> 5, lane = threadIdx.x & 31;
    const int row = blockIdx.x * 8 + warp;
    float s = 0.f;
    #pragma unroll
    for (int k = lane; k < HH; k += 32) s += h[row * HH + k] * Wd[k];
    #pragma unroll
    for (int o = 16; o; o >>= 1) s += __shfl_xor_sync(0xffffffffu, s, o);
    if (lane == 0) out[row] = sigf(s + bd[0]);
}

extern "C" void kernel_launch(void* const* d_in, const int* in_sizes, int n_in,
                              void* d_out, int out_size) {
    const float* x  = (const float*)d_in[0];
    const float* W  = (const float*)d_in[1];
    const float* U  = (const float*)d_in[2];
    const float* b  = (const float*)d_in[3];
    const float* Wd = (const float*)d_in[4];
    const float* bd = (const float*)d_in[5];

    cudaFuncSetAttribute(zx_gemm, cudaFuncAttributeMaxDynamicSharedMemorySize, 104448);
    cudaFuncSetAttribute(lstm_persist, cudaFuncAttributeMaxDynamicSharedMemorySize, SM_TOT);

    mask_kernel<<<BB * TT / 8, 256>>>(x);
    zx_gemm<<<dim3(32, BB * 4), 128, 104448>>>(x, W, b);
    zero_cnt<<<1, 32>>>();
    lstm_persist<<<NBLK, 128, SM_TOT>>>(U);
    head_kernel<<<BB / 8, 256>>>(Wd, bd, (float*)d_out);
}